// round 2
// baseline (speedup 1.0000x reference)
#include <cuda_runtime.h>
#include <stdint.h>

// Loihi CUBA constants
#define AI 0.75f       // (4096-1024)/4096
#define AV 0.96875f    // (4096-128)/4096
#define TH 100.0f

// ---------------------------------------------------------------------------
// Bitpacked spike buffers: bit k of word j (of 4) = spike at t = j*32 + k.
// All intermediate buffers store the DELAYED stream (128-bit <<1 done at
// producer write time).
// ---------------------------------------------------------------------------
__device__ uint32_t g_s0[16 * 2  * 40 * 40 * 4];   // packed raw input spikes
__device__ uint32_t g_s1[16 * 8  * 40 * 40 * 4];   // conv1+LIF out (delayed)
__device__ uint32_t g_s2[16 * 8  * 20 * 20 * 4];   // pool1+LIF out (delayed)
__device__ uint32_t g_s3[16 * 16 * 20 * 20 * 4];   // conv2+LIF out (delayed)
__device__ uint32_t g_s4[16 * 16 * 10 * 10 * 4];   // pool2+LIF out (delayed)
__device__ float2   g_m5[16 * 3200 * 64];          // conv3+LIF out as float2 t-pair masks (delayed)
__device__ float    g_x6p[2 * 16 * 512 * 128];     // fc pre-activations (2 c-split partials)

// ---------------------------------------------------------------------------
// K0: pack raw float spikes [16,2,40,40,128] (t contiguous) -> bit words
// ---------------------------------------------------------------------------
__global__ void k_pack(const float* __restrict__ sp) {
    int idx = blockIdx.x * blockDim.x + threadIdx.x;   // (n,c,h,w), 51200 total
    const float4* p = (const float4*)(sp + (size_t)idx * 128);
    uint32_t w[4];
#pragma unroll
    for (int j = 0; j < 4; j++) {
        uint32_t b = 0;
#pragma unroll
        for (int q = 0; q < 8; q++) {
            float4 v = p[j * 8 + q];
            b |= (v.x > 0.5f ? 1u : 0u) << (q * 4 + 0);
            b |= (v.y > 0.5f ? 1u : 0u) << (q * 4 + 1);
            b |= (v.z > 0.5f ? 1u : 0u) << (q * 4 + 2);
            b |= (v.w > 0.5f ? 1u : 0u) << (q * 4 + 3);
        }
        w[j] = b;
    }
    *((uint4*)&g_s0[(size_t)idx * 4]) = make_uint4(w[0], w[1], w[2], w[3]);
}

// ---------------------------------------------------------------------------
// K1: conv1 (2->8, 3x3, pad1, w*20) + LIF -> g_s1 (delayed)
// grid = 16n * 40h ; block = 40w * 8o = 320 threads
// ---------------------------------------------------------------------------
__global__ void k_conv1(const float* __restrict__ cw) {
    __shared__ uint32_t sh[2 * 3 * 42 * 4];  // [c][dy][wx(42, halo)][j]
    int b = blockIdx.x;
    int n = b / 40, h = b % 40;
    int tid = threadIdx.x;

    for (int i = tid; i < 2 * 3 * 42 * 4; i += 320) {
        int j = i & 3;
        int t2 = i >> 2;
        int wx = t2 % 42;
        int t3 = t2 / 42;
        int dy = t3 % 3;
        int c  = t3 / 3;
        int r = h - 1 + dy, ws = wx - 1;
        uint32_t v = 0;
        if (r >= 0 && r < 40 && ws >= 0 && ws < 40)
            v = g_s0[(((n * 2 + c) * 40 + r) * 40 + ws) * 4 + j];
        sh[i] = v;
    }
    __syncthreads();

    int w = tid % 40, o = tid / 40;
    float wg[18];
#pragma unroll
    for (int i = 0; i < 18; i++) wg[i] = cw[o * 18 + i] * 20.0f;

    float u = 0.f, v = 0.f;
    uint32_t ow[4];
#pragma unroll
    for (int j = 0; j < 4; j++) {
        float acc[32];
#pragma unroll
        for (int k = 0; k < 32; k++) acc[k] = 0.f;
#pragma unroll
        for (int c = 0; c < 2; c++)
#pragma unroll
        for (int dy = 0; dy < 3; dy++)
#pragma unroll
        for (int dx = 0; dx < 3; dx++) {
            uint32_t wd = sh[(((c * 3 + dy) * 42) + (w + dx)) * 4 + j];
            float wt = wg[c * 9 + dy * 3 + dx];
#pragma unroll
            for (int k = 0; k < 32; k++)
                if (wd & (1u << k)) acc[k] += wt;
        }
        uint32_t bits = 0;
#pragma unroll
        for (int k = 0; k < 32; k++) {
            u = AI * u + acc[k];
            v = AV * v + u;
            if (v >= TH) { bits |= 1u << k; v = 0.f; }
        }
        ow[j] = bits;
    }
    uint32_t d0 = ow[0] << 1;
    uint32_t d1 = (ow[1] << 1) | (ow[0] >> 31);
    uint32_t d2 = (ow[2] << 1) | (ow[1] >> 31);
    uint32_t d3 = (ow[3] << 1) | (ow[2] >> 31);
    *((uint4*)&g_s1[((((n * 8 + o) * 40 + h) * 40 + w)) * 4]) = make_uint4(d0, d1, d2, d3);
}

// ---------------------------------------------------------------------------
// K2: 2x2 sum pool (* pool_w scalar) + LIF -> out (delayed). Generic.
// ---------------------------------------------------------------------------
__global__ void k_pool(const uint32_t* __restrict__ in, uint32_t* __restrict__ out,
                       int C, int Hin, const float* __restrict__ pw) {
    int Ho = Hin / 2;
    int idx = blockIdx.x * blockDim.x + threadIdx.x;   // (n,c,ph,pw)
    int pwi = idx % Ho;
    int t = idx / Ho;
    int phi = t % Ho; t /= Ho;
    int c = t % C;
    int n = t / C;
    float scale = pw[0];

    const uint32_t* b00 = &in[((((n * C + c) * Hin + 2 * phi) * Hin) + 2 * pwi) * 4];
    const uint32_t* b10 = b00 + Hin * 4;

    float u = 0.f, v = 0.f;
    uint32_t ow[4];
#pragma unroll
    for (int j = 0; j < 4; j++) {
        uint32_t a = b00[j], bb = b00[4 + j], cc = b10[j], d = b10[4 + j];
        uint32_t bits = 0;
#pragma unroll
        for (int k = 0; k < 32; k++) {
            int cnt = (int)((a >> k) & 1u) + (int)((bb >> k) & 1u)
                    + (int)((cc >> k) & 1u) + (int)((d >> k) & 1u);
            float x = (float)cnt * scale;
            u = AI * u + x;
            v = AV * v + u;
            if (v >= TH) { bits |= 1u << k; v = 0.f; }
        }
        ow[j] = bits;
    }
    uint32_t d0 = ow[0] << 1;
    uint32_t d1 = (ow[1] << 1) | (ow[0] >> 31);
    uint32_t d2 = (ow[2] << 1) | (ow[1] >> 31);
    uint32_t d3 = (ow[3] << 1) | (ow[2] >> 31);
    *((uint4*)&out[(size_t)idx * 4]) = make_uint4(d0, d1, d2, d3);
}

// ---------------------------------------------------------------------------
// K3/K5: generic 3x3 conv (pad 1) on bitpacked spikes + LIF (delayed output).
// MASK=false: write bit words. MASK=true: write float2 t-pair masks (fc layout).
// grid = (Cout/OPB, 16n) ; block = OPB * H * H threads.
// ---------------------------------------------------------------------------
template <int CIN, int H, int OPB, bool MASK>
__global__ void k_conv(const uint32_t* __restrict__ in, void* __restrict__ outp,
                       const float* __restrict__ wsrc, float wscale, int Cout) {
    constexpr int PH = H + 2;
    constexpr int INW = CIN * PH * PH * 4;
    extern __shared__ uint32_t sh[];
    float* shw = (float*)&sh[INW];  // OPB*CIN*9 scaled weights

    int og = blockIdx.x, n = blockIdx.y;
    int tid = threadIdx.x;
    int nth = blockDim.x;

    for (int i = tid; i < INW; i += nth) sh[i] = 0u;
    __syncthreads();
    for (int i = tid; i < CIN * H * H * 4; i += nth) {
        int j = i & 3;
        int t = i >> 2;
        int w = t % H; t /= H;
        int h = t % H;
        int c = t / H;
        sh[(((c * PH + h + 1) * PH) + (w + 1)) * 4 + j] =
            in[(((n * CIN + c) * H * H) + h * H + w) * 4 + j];
    }
    for (int i = tid; i < OPB * CIN * 9; i += nth)
        shw[i] = wsrc[og * OPB * CIN * 9 + i] * wscale;
    __syncthreads();

    int w = tid % H;
    int h = (tid / H) % H;
    int ol = tid / (H * H);

    float u = 0.f, v = 0.f;
    uint32_t ow[4];
#pragma unroll
    for (int j = 0; j < 4; j++) {
        float acc[32];
#pragma unroll
        for (int k = 0; k < 32; k++) acc[k] = 0.f;
        for (int c = 0; c < CIN; c++) {
            const uint32_t* base = &sh[((c * PH + h) * PH + w) * 4 + j];
            const float* wp = &shw[(ol * CIN + c) * 9];
#pragma unroll
            for (int dy = 0; dy < 3; dy++)
#pragma unroll
            for (int dx = 0; dx < 3; dx++) {
                uint32_t wd = base[(dy * PH + dx) * 4];
                float wt = wp[dy * 3 + dx];
#pragma unroll
                for (int k = 0; k < 32; k++)
                    if (wd & (1u << k)) acc[k] += wt;
            }
        }
        uint32_t bits = 0;
#pragma unroll
        for (int k = 0; k < 32; k++) {
            u = AI * u + acc[k];
            v = AV * v + u;
            if (v >= TH) { bits |= 1u << k; v = 0.f; }
        }
        ow[j] = bits;
    }
    int o = og * OPB + ol;
    uint32_t d0 = ow[0] << 1;
    uint32_t d1 = (ow[1] << 1) | (ow[0] >> 31);
    uint32_t d2 = (ow[2] << 1) | (ow[1] >> 31);
    uint32_t d3 = (ow[3] << 1) | (ow[2] >> 31);

    if (!MASK) {
        uint32_t* out = (uint32_t*)outp;
        *((uint4*)&out[(((size_t)(n * Cout + o) * H * H) + h * H + w) * 4]) =
            make_uint4(d0, d1, d2, d3);
    } else {
        // write float2 t-pair masks: m5[n][c][q], q = j*16 + p, pair t = {2q, 2q+1}
        float2* mrow = (float2*)outp +
                       ((size_t)n * (Cout * H * H) + (size_t)o * H * H + h * H + w) * 64;
        uint32_t d[4] = {d0, d1, d2, d3};
#pragma unroll
        for (int jj = 0; jj < 4; jj++) {
            uint32_t wd = d[jj];
#pragma unroll
            for (int p = 0; p < 16; p += 2) {
                float4 vv;
                vv.x = (wd >> (2 * p))     & 1u ? 1.f : 0.f;
                vv.y = (wd >> (2 * p + 1)) & 1u ? 1.f : 0.f;
                vv.z = (wd >> (2 * p + 2)) & 1u ? 1.f : 0.f;
                vv.w = (wd >> (2 * p + 3)) & 1u ? 1.f : 0.f;
                *(float4*)(mrow + jj * 16 + p) = vv;
            }
        }
    }
}

// ---------------------------------------------------------------------------
// K6: fc partial pre-activation via packed f32x2 FFMA on float spike masks.
// x6p[cs][n][o][t] = sum_{c in half cs} W[o,c] * mask[n][c][t]
// grid = (8 o-blocks, 16 n, 2 c-halves); block = 256 = 64 o x 4 j.
// Shared mask chunk: 64 c rows, each row = 4 j-slices of 16 pairs, j-stride 18
// (pad) -> conflict-free LDS.128 across the warp's 4 j-groups.
// ---------------------------------------------------------------------------
__global__ void __launch_bounds__(256) k_fc(const float2* __restrict__ m5,
                                            const float* __restrict__ W,
                                            float* __restrict__ x6p) {
    __shared__ __align__(16) float2 sm[64 * 72];   // 36864 B

    int ob = blockIdx.x, n = blockIdx.y, cs = blockIdx.z;
    int tid = threadIdx.x;
    int ol = tid >> 2;     // 0..63
    int j  = tid & 3;      // 0..3
    int o  = ob * 64 + ol;

    const float*  wrow = W  + (size_t)o * 3200 + (size_t)cs * 1600;
    const float2* mb   = m5 + ((size_t)n * 3200 + (size_t)cs * 1600) * 64;

    unsigned long long acc[16];
#pragma unroll
    for (int p = 0; p < 16; p++) acc[p] = 0ull;

    for (int cb = 0; cb < 1600; cb += 64) {
        __syncthreads();
        // stage 64 c rows (4096 float2) into swizzled shared, float4 loads
        const float4* src4 = (const float4*)(mb + (size_t)cb * 64);
#pragma unroll
        for (int r = 0; r < 8; r++) {
            int i4 = tid + r * 256;         // 0..2047
            float4 v = src4[i4];
            int i = i4 * 2;
            int cl = i >> 6;
            int q = i & 63;                  // q even -> q,q+1 share j-slice
            float2* dst = &sm[cl * 72 + (q >> 4) * 18 + (q & 15)];
            dst[0] = make_float2(v.x, v.y);
            dst[1] = make_float2(v.z, v.w);
        }
        __syncthreads();

        const float2* myrow0 = &sm[j * 18];
#pragma unroll 2
        for (int c = 0; c < 64; c += 4) {
            float4 w4 = *(const float4*)(wrow + cb + c);
            float ws[4] = {w4.x, w4.y, w4.z, w4.w};
#pragma unroll
            for (int s = 0; s < 4; s++) {
                unsigned long long w2;
                asm("mov.b64 %0, {%1, %1};" : "=l"(w2) : "f"(ws[s]));
                const ulonglong2* row = (const ulonglong2*)(myrow0 + (c + s) * 72);
#pragma unroll
                for (int p = 0; p < 8; p++) {
                    ulonglong2 mm = row[p];   // LDS.128: 2 t-pair masks
                    asm("fma.rn.f32x2 %0, %1, %2, %0;" : "+l"(acc[2 * p])     : "l"(mm.x), "l"(w2));
                    asm("fma.rn.f32x2 %0, %1, %2, %0;" : "+l"(acc[2 * p + 1]) : "l"(mm.y), "l"(w2));
                }
            }
        }
    }

    // acc[p] = t-pair (j*16+p) -> floats t = j*32+2p, j*32+2p+1
    unsigned long long* xp = (unsigned long long*)
        (x6p + (((size_t)cs * 16 + n) * 512 + o) * 128 + j * 32);
#pragma unroll
    for (int p = 0; p < 16; p++) xp[p] = acc[p];
}

// ---------------------------------------------------------------------------
// K7: final LIF over (x6p part0 + part1) + output delay-shift -> d_out
// ---------------------------------------------------------------------------
__global__ void k_lif_out(const float* __restrict__ x6p, float* __restrict__ out) {
    int idx = blockIdx.x * blockDim.x + threadIdx.x;   // (n,o), 8192 total
    const float* a = &x6p[(size_t)idx * 128];
    const float* b = a + (size_t)16 * 512 * 128;
    float* op = &out[(size_t)idx * 128];
    float u = 0.f, v = 0.f, prev = 0.f;
#pragma unroll 8
    for (int t = 0; t < 128; t++) {
        op[t] = prev;
        u = AI * u + (a[t] + b[t]);
        v = AV * v + u;
        if (v >= TH) { prev = 1.f; v = 0.f; } else { prev = 0.f; }
    }
}

// ---------------------------------------------------------------------------
extern "C" void kernel_launch(void* const* d_in, const int* in_sizes, int n_in,
                              void* d_out, int out_size) {
    const float* spike = (const float*)d_in[0];
    const float* c1w   = (const float*)d_in[1];
    const float* c2w   = (const float*)d_in[2];
    const float* c3w   = (const float*)d_in[3];
    const float* p1w   = (const float*)d_in[4];
    const float* p2w   = (const float*)d_in[5];
    const float* fcw   = (const float*)d_in[6];
    float* out = (float*)d_out;

    uint32_t *s1, *s2, *s3, *s4;
    float2* m5;
    float* x6p;
    cudaGetSymbolAddress((void**)&s1, g_s1);
    cudaGetSymbolAddress((void**)&s2, g_s2);
    cudaGetSymbolAddress((void**)&s3, g_s3);
    cudaGetSymbolAddress((void**)&s4, g_s4);
    cudaGetSymbolAddress((void**)&m5, g_m5);
    cudaGetSymbolAddress((void**)&x6p, g_x6p);

    // conv2 needs ~62.5KB dynamic shared
    cudaFuncSetAttribute((const void*)k_conv<8, 20, 2, false>,
                         cudaFuncAttributeMaxDynamicSharedMemorySize, 65536);
    cudaFuncSetAttribute((const void*)k_conv<16, 10, 2, true>,
                         cudaFuncAttributeMaxDynamicSharedMemorySize, 49152);

    k_pack<<<200, 256>>>(spike);
    k_conv1<<<640, 320>>>(c1w);
    k_pool<<<200, 256>>>(s1, s2, 8, 40, p1w);
    k_conv<8, 20, 2, false><<<dim3(8, 16), 800, 62528>>>(s2, (void*)s3, c2w, 100.0f, 16);
    k_pool<<<100, 256>>>(s3, s4, 16, 20, p2w);
    // conv3: OPB=2 -> 256 blocks (was 64), writes float2 masks for the FC
    k_conv<16, 10, 2, true><<<dim3(16, 16), 200, 38016>>>(s4, (void*)m5, c3w, 100.0f, 32);
    k_fc<<<dim3(8, 16, 2), 256>>>(m5, fcw, x6p);
    k_lif_out<<<32, 256>>>(x6p, out);
}

// round 3
// speedup vs baseline: 1.6130x; 1.6130x over previous
#include <cuda_runtime.h>
#include <stdint.h>

// Loihi CUBA constants
#define AI 0.75f       // (4096-1024)/4096
#define AV 0.96875f    // (4096-128)/4096
#define TH 100.0f

// ---------------------------------------------------------------------------
// Bitpacked spike buffers: bit k of word j (of 4) = spike at t = j*32 + k.
// All intermediate buffers store the DELAYED stream (128-bit <<1 done at
// producer write time).
// ---------------------------------------------------------------------------
__device__ uint32_t g_s0[16 * 2  * 40 * 40 * 4];   // packed raw input spikes
__device__ uint32_t g_s1[16 * 8  * 40 * 40 * 4];   // conv1+LIF out (delayed)
__device__ uint32_t g_s2[16 * 8  * 20 * 20 * 4];   // pool1+LIF out (delayed)
__device__ uint32_t g_s3[16 * 16 * 20 * 20 * 4];   // conv2+LIF out (delayed)
__device__ uint32_t g_s4[16 * 16 * 10 * 10 * 4];   // pool2+LIF out (delayed)
__device__ uint32_t g_s5[16 * 3200 * 4];           // conv3+LIF out (delayed, t-major bits)
__device__ uint32_t g_sb[16 * 128 * 100];          // transposed: c-major bit words per (n,t)
__device__ float    g_x6p[4 * 16 * 512 * 128];     // fc pre-activations (4 c-quarter partials)

// ---------------------------------------------------------------------------
// K0: pack raw float spikes [16,2,40,40,128] (t contiguous) -> bit words
// ---------------------------------------------------------------------------
__global__ void k_pack(const float* __restrict__ sp) {
    int idx = blockIdx.x * blockDim.x + threadIdx.x;   // (n,c,h,w), 51200 total
    const float4* p = (const float4*)(sp + (size_t)idx * 128);
    uint32_t w[4];
#pragma unroll
    for (int j = 0; j < 4; j++) {
        uint32_t b = 0;
#pragma unroll
        for (int q = 0; q < 8; q++) {
            float4 v = p[j * 8 + q];
            b |= (v.x > 0.5f ? 1u : 0u) << (q * 4 + 0);
            b |= (v.y > 0.5f ? 1u : 0u) << (q * 4 + 1);
            b |= (v.z > 0.5f ? 1u : 0u) << (q * 4 + 2);
            b |= (v.w > 0.5f ? 1u : 0u) << (q * 4 + 3);
        }
        w[j] = b;
    }
    *((uint4*)&g_s0[(size_t)idx * 4]) = make_uint4(w[0], w[1], w[2], w[3]);
}

// ---------------------------------------------------------------------------
// K1: conv1 (2->8, 3x3, pad1, w*20) + LIF -> g_s1 (delayed)
// grid = 16n * 40h ; block = 40w * 8o = 320 threads
// ---------------------------------------------------------------------------
__global__ void k_conv1(const float* __restrict__ cw) {
    __shared__ uint32_t sh[2 * 3 * 42 * 4];  // [c][dy][wx(42, halo)][j]
    int b = blockIdx.x;
    int n = b / 40, h = b % 40;
    int tid = threadIdx.x;

    for (int i = tid; i < 2 * 3 * 42 * 4; i += 320) {
        int j = i & 3;
        int t2 = i >> 2;
        int wx = t2 % 42;
        int t3 = t2 / 42;
        int dy = t3 % 3;
        int c  = t3 / 3;
        int r = h - 1 + dy, ws = wx - 1;
        uint32_t v = 0;
        if (r >= 0 && r < 40 && ws >= 0 && ws < 40)
            v = g_s0[(((n * 2 + c) * 40 + r) * 40 + ws) * 4 + j];
        sh[i] = v;
    }
    __syncthreads();

    int w = tid % 40, o = tid / 40;
    float wg[18];
#pragma unroll
    for (int i = 0; i < 18; i++) wg[i] = cw[o * 18 + i] * 20.0f;

    float u = 0.f, v = 0.f;
    uint32_t ow[4];
#pragma unroll
    for (int j = 0; j < 4; j++) {
        float acc[32];
#pragma unroll
        for (int k = 0; k < 32; k++) acc[k] = 0.f;
#pragma unroll
        for (int c = 0; c < 2; c++)
#pragma unroll
        for (int dy = 0; dy < 3; dy++)
#pragma unroll
        for (int dx = 0; dx < 3; dx++) {
            uint32_t wd = sh[(((c * 3 + dy) * 42) + (w + dx)) * 4 + j];
            float wt = wg[c * 9 + dy * 3 + dx];
#pragma unroll
            for (int k = 0; k < 32; k++)
                if (wd & (1u << k)) acc[k] += wt;
        }
        uint32_t bits = 0;
#pragma unroll
        for (int k = 0; k < 32; k++) {
            u = AI * u + acc[k];
            v = AV * v + u;
            if (v >= TH) { bits |= 1u << k; v = 0.f; }
        }
        ow[j] = bits;
    }
    uint32_t d0 = ow[0] << 1;
    uint32_t d1 = (ow[1] << 1) | (ow[0] >> 31);
    uint32_t d2 = (ow[2] << 1) | (ow[1] >> 31);
    uint32_t d3 = (ow[3] << 1) | (ow[2] >> 31);
    *((uint4*)&g_s1[((((n * 8 + o) * 40 + h) * 40 + w)) * 4]) = make_uint4(d0, d1, d2, d3);
}

// ---------------------------------------------------------------------------
// K2: 2x2 sum pool (* pool_w scalar) + LIF -> out (delayed). Generic.
// ---------------------------------------------------------------------------
__global__ void k_pool(const uint32_t* __restrict__ in, uint32_t* __restrict__ out,
                       int C, int Hin, const float* __restrict__ pw) {
    int Ho = Hin / 2;
    int idx = blockIdx.x * blockDim.x + threadIdx.x;   // (n,c,ph,pw)
    int pwi = idx % Ho;
    int t = idx / Ho;
    int phi = t % Ho; t /= Ho;
    int c = t % C;
    int n = t / C;
    float scale = pw[0];

    const uint32_t* b00 = &in[((((n * C + c) * Hin + 2 * phi) * Hin) + 2 * pwi) * 4];
    const uint32_t* b10 = b00 + Hin * 4;

    float u = 0.f, v = 0.f;
    uint32_t ow[4];
#pragma unroll
    for (int j = 0; j < 4; j++) {
        uint32_t a = b00[j], bb = b00[4 + j], cc = b10[j], d = b10[4 + j];
        uint32_t bits = 0;
#pragma unroll
        for (int k = 0; k < 32; k++) {
            int cnt = (int)((a >> k) & 1u) + (int)((bb >> k) & 1u)
                    + (int)((cc >> k) & 1u) + (int)((d >> k) & 1u);
            float x = (float)cnt * scale;
            u = AI * u + x;
            v = AV * v + u;
            if (v >= TH) { bits |= 1u << k; v = 0.f; }
        }
        ow[j] = bits;
    }
    uint32_t d0 = ow[0] << 1;
    uint32_t d1 = (ow[1] << 1) | (ow[0] >> 31);
    uint32_t d2 = (ow[2] << 1) | (ow[1] >> 31);
    uint32_t d3 = (ow[3] << 1) | (ow[2] >> 31);
    *((uint4*)&out[(size_t)idx * 4]) = make_uint4(d0, d1, d2, d3);
}

// ---------------------------------------------------------------------------
// K3/K5: generic 3x3 conv (pad 1) on bitpacked spikes + LIF -> out (delayed).
// grid = (Cout/OPB, 16n) ; block = OPB * H * H threads.
// ---------------------------------------------------------------------------
template <int CIN, int H, int OPB>
__global__ void k_conv(const uint32_t* __restrict__ in, uint32_t* __restrict__ out,
                       const float* __restrict__ wsrc, float wscale, int Cout) {
    constexpr int PH = H + 2;
    constexpr int INW = CIN * PH * PH * 4;
    extern __shared__ uint32_t sh[];
    float* shw = (float*)&sh[INW];  // OPB*CIN*9 scaled weights

    int og = blockIdx.x, n = blockIdx.y;
    int tid = threadIdx.x;
    int nth = blockDim.x;

    for (int i = tid; i < INW; i += nth) sh[i] = 0u;
    __syncthreads();
    for (int i = tid; i < CIN * H * H * 4; i += nth) {
        int j = i & 3;
        int t = i >> 2;
        int w = t % H; t /= H;
        int h = t % H;
        int c = t / H;
        sh[(((c * PH + h + 1) * PH) + (w + 1)) * 4 + j] =
            in[(((n * CIN + c) * H * H) + h * H + w) * 4 + j];
    }
    for (int i = tid; i < OPB * CIN * 9; i += nth)
        shw[i] = wsrc[og * OPB * CIN * 9 + i] * wscale;
    __syncthreads();

    int w = tid % H;
    int h = (tid / H) % H;
    int ol = tid / (H * H);

    float u = 0.f, v = 0.f;
    uint32_t ow[4];
#pragma unroll
    for (int j = 0; j < 4; j++) {
        float acc[32];
#pragma unroll
        for (int k = 0; k < 32; k++) acc[k] = 0.f;
        for (int c = 0; c < CIN; c++) {
            const uint32_t* base = &sh[((c * PH + h) * PH + w) * 4 + j];
            const float* wp = &shw[(ol * CIN + c) * 9];
#pragma unroll
            for (int dy = 0; dy < 3; dy++)
#pragma unroll
            for (int dx = 0; dx < 3; dx++) {
                uint32_t wd = base[(dy * PH + dx) * 4];
                float wt = wp[dy * 3 + dx];
#pragma unroll
                for (int k = 0; k < 32; k++)
                    if (wd & (1u << k)) acc[k] += wt;
            }
        }
        uint32_t bits = 0;
#pragma unroll
        for (int k = 0; k < 32; k++) {
            u = AI * u + acc[k];
            v = AV * v + u;
            if (v >= TH) { bits |= 1u << k; v = 0.f; }
        }
        ow[j] = bits;
    }
    int o = og * OPB + ol;
    uint32_t d0 = ow[0] << 1;
    uint32_t d1 = (ow[1] << 1) | (ow[0] >> 31);
    uint32_t d2 = (ow[2] << 1) | (ow[1] >> 31);
    uint32_t d3 = (ow[3] << 1) | (ow[2] >> 31);
    *((uint4*)&out[(((size_t)(n * Cout + o) * H * H) + h * H + w) * 4]) =
        make_uint4(d0, d1, d2, d3);
}

// ---------------------------------------------------------------------------
// K5b: bit transpose t-major -> c-major via ballot.
// g_s5[n][c][j] (bit k = t j*32+k) -> g_sb[n][t][cw] (bit i = c cw*32+i)
// One warp per (n, cw, j): 6400 warps.
// ---------------------------------------------------------------------------
__global__ void k_trans() {
    int gw = (blockIdx.x * blockDim.x + threadIdx.x) >> 5;   // 0..6399
    int lane = threadIdx.x & 31;
    int n = gw / 400;
    int r = gw % 400;
    int cw = r >> 2;
    int j = r & 3;
    uint32_t w = g_s5[((size_t)n * 3200 + cw * 32 + lane) * 4 + j];
    uint32_t out = 0;
#pragma unroll
    for (int b = 0; b < 32; b++) {
        uint32_t bl = __ballot_sync(0xffffffffu, (w >> b) & 1u);
        if (lane == b) out = bl;
    }
    g_sb[((size_t)n * 128 + j * 32 + lane) * 100 + cw] = out;
}

// ---------------------------------------------------------------------------
// K6: sparse FC. grid = (4 tt, 16 n, 4 cs); block = 512 threads = 512 o.
// Each block: c-range [cs*800, cs*800+800), t-range [tt*32, tt*32+32).
// W chunk [32 c][512 o] staged in 64KB dynamic shared; bit words warp-uniform
// -> divergence-free sparse while loop. Skipping zero adds is bit-exact.
// ---------------------------------------------------------------------------
__global__ void __launch_bounds__(512) k_fcs(const float* __restrict__ W,
                                             float* __restrict__ x6p) {
    extern __shared__ float shW[];          // [32][512] = 64KB
    __shared__ uint32_t shB[32 * 25];       // bit words [b][cc]

    int tt = blockIdx.x, n = blockIdx.y, cs = blockIdx.z;
    int tid = threadIdx.x;                  // = o

    for (int i = tid; i < 32 * 25; i += 512) {
        int b = i / 25, cc = i % 25;
        shB[i] = g_sb[((size_t)n * 128 + tt * 32 + b) * 100 + cs * 25 + cc];
    }

    float acc[32];
#pragma unroll
    for (int b = 0; b < 32; b++) acc[b] = 0.f;

    const float* wbase = W + (size_t)tid * 3200 + cs * 800;

    for (int cc = 0; cc < 25; cc++) {
        __syncthreads();
        const float4* wp = (const float4*)(wbase + cc * 32);
#pragma unroll
        for (int q = 0; q < 8; q++) {
            float4 v = wp[q];
            shW[(q * 4 + 0) * 512 + tid] = v.x;
            shW[(q * 4 + 1) * 512 + tid] = v.y;
            shW[(q * 4 + 2) * 512 + tid] = v.z;
            shW[(q * 4 + 3) * 512 + tid] = v.w;
        }
        __syncthreads();

#pragma unroll
        for (int b = 0; b < 32; b++) {
            uint32_t s = shB[b * 25 + cc];
            while (s) {
                int k = __ffs(s) - 1;
                s &= s - 1;
                acc[b] += shW[k * 512 + tid];
            }
        }
    }

    float* xp = x6p + (((size_t)cs * 16 + n) * 512 + tid) * 128 + tt * 32;
#pragma unroll
    for (int b = 0; b < 32; b++) xp[b] = acc[b];
}

// ---------------------------------------------------------------------------
// K7: final LIF over sum of 4 partials + output delay-shift -> d_out
// ---------------------------------------------------------------------------
__global__ void k_lif_out(const float* __restrict__ x6p, float* __restrict__ out) {
    const size_t S = (size_t)16 * 512 * 128;
    int idx = blockIdx.x * blockDim.x + threadIdx.x;   // (n,o), 8192 total
    const float* a = &x6p[(size_t)idx * 128];
    float* op = &out[(size_t)idx * 128];
    float u = 0.f, v = 0.f, prev = 0.f;
#pragma unroll 8
    for (int t = 0; t < 128; t++) {
        op[t] = prev;
        float x = (a[t] + a[t + S]) + (a[t + 2 * S] + a[t + 3 * S]);
        u = AI * u + x;
        v = AV * v + u;
        if (v >= TH) { prev = 1.f; v = 0.f; } else { prev = 0.f; }
    }
}

// ---------------------------------------------------------------------------
extern "C" void kernel_launch(void* const* d_in, const int* in_sizes, int n_in,
                              void* d_out, int out_size) {
    const float* spike = (const float*)d_in[0];
    const float* c1w   = (const float*)d_in[1];
    const float* c2w   = (const float*)d_in[2];
    const float* c3w   = (const float*)d_in[3];
    const float* p1w   = (const float*)d_in[4];
    const float* p2w   = (const float*)d_in[5];
    const float* fcw   = (const float*)d_in[6];
    float* out = (float*)d_out;

    uint32_t *s1, *s2, *s3, *s4, *s5;
    float* x6p;
    cudaGetSymbolAddress((void**)&s1, g_s1);
    cudaGetSymbolAddress((void**)&s2, g_s2);
    cudaGetSymbolAddress((void**)&s3, g_s3);
    cudaGetSymbolAddress((void**)&s4, g_s4);
    cudaGetSymbolAddress((void**)&s5, g_s5);
    cudaGetSymbolAddress((void**)&x6p, g_x6p);

    cudaFuncSetAttribute((const void*)k_conv<8, 20, 2>,
                         cudaFuncAttributeMaxDynamicSharedMemorySize, 65536);
    cudaFuncSetAttribute((const void*)k_conv<16, 10, 2>,
                         cudaFuncAttributeMaxDynamicSharedMemorySize, 49152);
    cudaFuncSetAttribute((const void*)k_fcs,
                         cudaFuncAttributeMaxDynamicSharedMemorySize, 65536);

    k_pack<<<200, 256>>>(spike);
    k_conv1<<<640, 320>>>(c1w);
    k_pool<<<200, 256>>>(s1, s2, 8, 40, p1w);
    k_conv<8, 20, 2><<<dim3(8, 16), 800, 62528>>>(s2, s3, c2w, 100.0f, 16);
    k_pool<<<100, 256>>>(s3, s4, 16, 20, p2w);
    // conv3: OPB=2 -> 256 blocks
    k_conv<16, 10, 2><<<dim3(16, 16), 200, 38016>>>(s4, s5, c3w, 100.0f, 32);
    k_trans<<<800, 256>>>();
    k_fcs<<<dim3(4, 16, 4), 512, 65536>>>(fcw, x6p);
    k_lif_out<<<32, 256>>>(x6p, out);
}

// round 4
// speedup vs baseline: 2.2255x; 1.3798x over previous
#include <cuda_runtime.h>
#include <stdint.h>

// Loihi CUBA constants
#define AI 0.75f       // (4096-1024)/4096
#define AV 0.96875f    // (4096-128)/4096
#define TH 100.0f

// ---------------------------------------------------------------------------
// Bitpacked spike buffers: bit k of word j (of 4) = spike at t = j*32 + k.
// All intermediate buffers store the DELAYED stream (128-bit <<1 done at
// producer write time).
// ---------------------------------------------------------------------------
__device__ uint32_t g_s0[16 * 2  * 40 * 40 * 4];   // packed raw input spikes
__device__ uint32_t g_s1[16 * 8  * 40 * 40 * 4];   // conv1+LIF out (delayed)
__device__ uint32_t g_s2[16 * 8  * 20 * 20 * 4];   // pool1+LIF out (delayed)
__device__ uint32_t g_s3[16 * 16 * 20 * 20 * 4];   // conv2+LIF out (delayed)
__device__ uint32_t g_s4[16 * 16 * 10 * 10 * 4];   // pool2+LIF out (delayed)
__device__ uint32_t g_s5[16 * 3200 * 4];           // conv3+LIF out (delayed, t-major)
__device__ uint32_t g_sb[16 * 128 * 100];          // FC input: c-major words per (n,t)
// c-major padded spike images (pads stay zero: zero-init, never written)
__device__ uint8_t  g_cp1[16 * 22 * 22 * 128];     // pool1 out, 8 c bits per (n,py,px,t)
__device__ uint16_t g_cp2[16 * 12 * 12 * 128];     // pool2 out, 16 c bits per (n,py,px,t)
__device__ float    g_x6p[4 * 16 * 512 * 128];     // fc pre-activations (4 c-quarter partials)

// ---------------------------------------------------------------------------
// K0: pack raw float spikes [16,2,40,40,128] (t contiguous) -> bit words
// ---------------------------------------------------------------------------
__global__ void k_pack(const float* __restrict__ sp) {
    int idx = blockIdx.x * blockDim.x + threadIdx.x;   // (n,c,h,w), 51200 total
    const float4* p = (const float4*)(sp + (size_t)idx * 128);
    uint32_t w[4];
#pragma unroll
    for (int j = 0; j < 4; j++) {
        uint32_t b = 0;
#pragma unroll
        for (int q = 0; q < 8; q++) {
            float4 v = p[j * 8 + q];
            b |= (v.x > 0.5f ? 1u : 0u) << (q * 4 + 0);
            b |= (v.y > 0.5f ? 1u : 0u) << (q * 4 + 1);
            b |= (v.z > 0.5f ? 1u : 0u) << (q * 4 + 2);
            b |= (v.w > 0.5f ? 1u : 0u) << (q * 4 + 3);
        }
        w[j] = b;
    }
    *((uint4*)&g_s0[(size_t)idx * 4]) = make_uint4(w[0], w[1], w[2], w[3]);
}

// ---------------------------------------------------------------------------
// K1: conv1 (2->8, 3x3, pad1, w*20) + LIF -> g_s1 (delayed). Dense bit path.
// grid = 16n * 40h ; block = 40w * 8o = 320 threads
// ---------------------------------------------------------------------------
__global__ void k_conv1(const float* __restrict__ cw) {
    __shared__ uint32_t sh[2 * 3 * 42 * 4];  // [c][dy][wx(42, halo)][j]
    int b = blockIdx.x;
    int n = b / 40, h = b % 40;
    int tid = threadIdx.x;

    for (int i = tid; i < 2 * 3 * 42 * 4; i += 320) {
        int j = i & 3;
        int t2 = i >> 2;
        int wx = t2 % 42;
        int t3 = t2 / 42;
        int dy = t3 % 3;
        int c  = t3 / 3;
        int r = h - 1 + dy, ws = wx - 1;
        uint32_t v = 0;
        if (r >= 0 && r < 40 && ws >= 0 && ws < 40)
            v = g_s0[(((n * 2 + c) * 40 + r) * 40 + ws) * 4 + j];
        sh[i] = v;
    }
    __syncthreads();

    int w = tid % 40, o = tid / 40;
    float wg[18];
#pragma unroll
    for (int i = 0; i < 18; i++) wg[i] = cw[o * 18 + i] * 20.0f;

    float u = 0.f, v = 0.f;
    uint32_t ow[4];
#pragma unroll
    for (int j = 0; j < 4; j++) {
        float acc[32];
#pragma unroll
        for (int k = 0; k < 32; k++) acc[k] = 0.f;
#pragma unroll
        for (int c = 0; c < 2; c++)
#pragma unroll
        for (int dy = 0; dy < 3; dy++)
#pragma unroll
        for (int dx = 0; dx < 3; dx++) {
            uint32_t wd = sh[(((c * 3 + dy) * 42) + (w + dx)) * 4 + j];
            float wt = wg[c * 9 + dy * 3 + dx];
#pragma unroll
            for (int k = 0; k < 32; k++)
                if (wd & (1u << k)) acc[k] += wt;
        }
        uint32_t bits = 0;
#pragma unroll
        for (int k = 0; k < 32; k++) {
            u = AI * u + acc[k];
            v = AV * v + u;
            if (v >= TH) { bits |= 1u << k; v = 0.f; }
        }
        ow[j] = bits;
    }
    uint32_t d0 = ow[0] << 1;
    uint32_t d1 = (ow[1] << 1) | (ow[0] >> 31);
    uint32_t d2 = (ow[2] << 1) | (ow[1] >> 31);
    uint32_t d3 = (ow[3] << 1) | (ow[2] >> 31);
    *((uint4*)&g_s1[((((n * 8 + o) * 40 + h) * 40 + w)) * 4]) = make_uint4(d0, d1, d2, d3);
}

// ---------------------------------------------------------------------------
// K2: 2x2 sum pool (* pool_w scalar) + LIF -> out (delayed). Generic.
// ---------------------------------------------------------------------------
__global__ void k_pool(const uint32_t* __restrict__ in, uint32_t* __restrict__ out,
                       int C, int Hin, const float* __restrict__ pw) {
    int Ho = Hin / 2;
    int idx = blockIdx.x * blockDim.x + threadIdx.x;   // (n,c,ph,pw)
    int pwi = idx % Ho;
    int t = idx / Ho;
    int phi = t % Ho; t /= Ho;
    int c = t % C;
    int n = t / C;
    float scale = pw[0];

    const uint32_t* b00 = &in[((((n * C + c) * Hin + 2 * phi) * Hin) + 2 * pwi) * 4];
    const uint32_t* b10 = b00 + Hin * 4;

    float u = 0.f, v = 0.f;
    uint32_t ow[4];
#pragma unroll
    for (int j = 0; j < 4; j++) {
        uint32_t a = b00[j], bb = b00[4 + j], cc = b10[j], d = b10[4 + j];
        uint32_t bits = 0;
#pragma unroll
        for (int k = 0; k < 32; k++) {
            int cnt = (int)((a >> k) & 1u) + (int)((bb >> k) & 1u)
                    + (int)((cc >> k) & 1u) + (int)((d >> k) & 1u);
            float x = (float)cnt * scale;
            u = AI * u + x;
            v = AV * v + u;
            if (v >= TH) { bits |= 1u << k; v = 0.f; }
        }
        ow[j] = bits;
    }
    uint32_t d0 = ow[0] << 1;
    uint32_t d1 = (ow[1] << 1) | (ow[0] >> 31);
    uint32_t d2 = (ow[2] << 1) | (ow[1] >> 31);
    uint32_t d3 = (ow[3] << 1) | (ow[2] >> 31);
    *((uint4*)&out[(size_t)idx * 4]) = make_uint4(d0, d1, d2, d3);
}

// ---------------------------------------------------------------------------
// K2b: transpose pool1 out (t-major bits per c) -> c-major bytes, padded 22x22.
// thread = (n, px, j): builds 32 bytes (t = j*32+k).
// ---------------------------------------------------------------------------
__global__ void k_tr8() {
    int i = blockIdx.x * blockDim.x + threadIdx.x;   // 25600
    int n = i / 1600;
    int r = i % 1600;
    int px = r >> 2, j = r & 3;
    uint32_t wc[8];
#pragma unroll
    for (int c = 0; c < 8; c++)
        wc[c] = g_s2[((size_t)((n * 8 + c) * 400 + px)) * 4 + j];
    int h = px / 20, w = px % 20;
    uint8_t* dst = g_cp1 + ((size_t)n * 484 + (h + 1) * 22 + (w + 1)) * 128 + j * 32;
#pragma unroll
    for (int k = 0; k < 32; k += 4) {
        uint32_t v = 0;
#pragma unroll
        for (int q = 0; q < 4; q++) {
            uint32_t byte = 0;
#pragma unroll
            for (int c = 0; c < 8; c++)
                byte |= ((wc[c] >> (k + q)) & 1u) << c;
            v |= byte << (q * 8);
        }
        *(uint32_t*)(dst + k) = v;
    }
}

// ---------------------------------------------------------------------------
// K4b: transpose pool2 out -> c-major uint16, padded 12x12.
// thread = (n, px, j): builds 32 u16.
// ---------------------------------------------------------------------------
__global__ void k_tr16() {
    int i = blockIdx.x * blockDim.x + threadIdx.x;   // 6400
    int n = i / 400;
    int r = i % 400;
    int px = r >> 2, j = r & 3;
    uint32_t wc[16];
#pragma unroll
    for (int c = 0; c < 16; c++)
        wc[c] = g_s4[((size_t)((n * 16 + c) * 100 + px)) * 4 + j];
    int h = px / 10, w = px % 10;
    uint16_t* dst = g_cp2 + ((size_t)n * 144 + (h + 1) * 12 + (w + 1)) * 128 + j * 32;
#pragma unroll
    for (int k = 0; k < 32; k += 2) {
        uint32_t v = 0;
#pragma unroll
        for (int c = 0; c < 16; c++) {
            v |= ((wc[c] >> k) & 1u) << c;
            v |= ((wc[c] >> (k + 1)) & 1u) << (16 + c);
        }
        *(uint32_t*)(dst + k) = v;
    }
}

// ---------------------------------------------------------------------------
// K3: sparse conv2 (8->16, w*100) + LIF -> g_s3 (delayed t-major bits).
// grid = (400 px, 16 n); block 128 = 8 tq x 16 o. tap = (dy*3+dx)*8 + c.
// ---------------------------------------------------------------------------
__global__ void __launch_bounds__(128) k_conv2s(const float* __restrict__ wsrc) {
    __shared__ float    shW[72 * 16];
    __shared__ uint32_t shTW[128 * 3];
    __shared__ float    pre[16 * 129];
    int px = blockIdx.x, n = blockIdx.y;
    int h = px / 20, w = px % 20;
    int tid = threadIdx.x;

    for (int i = tid; i < 72 * 16; i += 128) {
        int o = i & 15, tap = i >> 4;
        int c = tap & 7, dydx = tap >> 3;
        shW[i] = wsrc[(o * 8 + c) * 9 + dydx] * 100.0f;
    }
    {   // build 3 tap words for t = tid
        const uint8_t* base = g_cp1 + ((size_t)n * 484 + h * 22 + w) * 128 + tid;
        uint32_t b[9];
#pragma unroll
        for (int dy = 0; dy < 3; dy++)
#pragma unroll
            for (int dx = 0; dx < 3; dx++)
                b[dy * 3 + dx] = base[(dy * 22 + dx) * 128];
        shTW[tid * 3 + 0] = b[0] | (b[1] << 8) | (b[2] << 16) | (b[3] << 24);
        shTW[tid * 3 + 1] = b[4] | (b[5] << 8) | (b[6] << 16) | (b[7] << 24);
        shTW[tid * 3 + 2] = b[8];
    }
    __syncthreads();

    int o = tid & 15, tq = tid >> 4;
#pragma unroll 4
    for (int i = 0; i < 16; i++) {
        int t = tq * 16 + i;
        uint32_t s0 = shTW[t * 3], s1 = shTW[t * 3 + 1], s2 = shTW[t * 3 + 2];
        float a = 0.f;
        while (s0) { int k = __ffs(s0) - 1; s0 &= s0 - 1; a += shW[k * 16 + o]; }
        while (s1) { int k = __ffs(s1) - 1; s1 &= s1 - 1; a += shW[(32 + k) * 16 + o]; }
        while (s2) { int k = __ffs(s2) - 1; s2 &= s2 - 1; a += shW[(64 + k) * 16 + o]; }
        pre[o * 129 + t] = a;
    }
    __syncthreads();

    if (tid < 16) {
        float u = 0.f, v = 0.f;
        uint32_t ow[4];
#pragma unroll
        for (int j = 0; j < 4; j++) {
            uint32_t bits = 0;
#pragma unroll
            for (int k = 0; k < 32; k++) {
                u = AI * u + pre[tid * 129 + j * 32 + k];
                v = AV * v + u;
                if (v >= TH) { bits |= 1u << k; v = 0.f; }
            }
            ow[j] = bits;
        }
        uint32_t d0 = ow[0] << 1;
        uint32_t d1 = (ow[1] << 1) | (ow[0] >> 31);
        uint32_t d2 = (ow[2] << 1) | (ow[1] >> 31);
        uint32_t d3 = (ow[3] << 1) | (ow[2] >> 31);
        *((uint4*)&g_s3[((size_t)((n * 16 + tid) * 400 + px)) * 4]) =
            make_uint4(d0, d1, d2, d3);
    }
}

// ---------------------------------------------------------------------------
// K5: sparse conv3 (16->32, w*100) + LIF -> g_s5 (delayed, fc c-index layout).
// grid = (100 px, 16 n); block 256 = 8 tq x 32 o. tap = (dy*3+dx)*16 + c.
// ---------------------------------------------------------------------------
__global__ void __launch_bounds__(256) k_conv3s(const float* __restrict__ wsrc) {
    __shared__ float    shW[144 * 32];
    __shared__ uint32_t shTW[128 * 5];
    __shared__ float    pre[32 * 129];
    int px = blockIdx.x, n = blockIdx.y;
    int h = px / 10, w = px % 10;
    int tid = threadIdx.x;

    for (int i = tid; i < 144 * 32; i += 256) {
        int o = i & 31, tap = i >> 5;
        int c = tap & 15, dydx = tap >> 4;
        shW[i] = wsrc[(o * 16 + c) * 9 + dydx] * 100.0f;
    }
    if (tid < 128) {
        const uint16_t* base = g_cp2 + ((size_t)n * 144 + h * 12 + w) * 128 + tid;
        uint32_t b[9];
#pragma unroll
        for (int dy = 0; dy < 3; dy++)
#pragma unroll
            for (int dx = 0; dx < 3; dx++)
                b[dy * 3 + dx] = base[(dy * 12 + dx) * 128];
        shTW[tid * 5 + 0] = b[0] | (b[1] << 16);
        shTW[tid * 5 + 1] = b[2] | (b[3] << 16);
        shTW[tid * 5 + 2] = b[4] | (b[5] << 16);
        shTW[tid * 5 + 3] = b[6] | (b[7] << 16);
        shTW[tid * 5 + 4] = b[8];
    }
    __syncthreads();

    int o = tid & 31, tq = tid >> 5;
#pragma unroll 4
    for (int i = 0; i < 16; i++) {
        int t = tq * 16 + i;
        float a = 0.f;
#pragma unroll
        for (int m = 0; m < 5; m++) {
            uint32_t s = shTW[t * 5 + m];
            while (s) { int k = __ffs(s) - 1; s &= s - 1; a += shW[(m * 32 + k) * 32 + o]; }
        }
        pre[o * 129 + t] = a;
    }
    __syncthreads();

    if (tid < 32) {
        float u = 0.f, v = 0.f;
        uint32_t ow[4];
#pragma unroll
        for (int j = 0; j < 4; j++) {
            uint32_t bits = 0;
#pragma unroll
            for (int k = 0; k < 32; k++) {
                u = AI * u + pre[tid * 129 + j * 32 + k];
                v = AV * v + u;
                if (v >= TH) { bits |= 1u << k; v = 0.f; }
            }
            ow[j] = bits;
        }
        uint32_t d0 = ow[0] << 1;
        uint32_t d1 = (ow[1] << 1) | (ow[0] >> 31);
        uint32_t d2 = (ow[2] << 1) | (ow[1] >> 31);
        uint32_t d3 = (ow[3] << 1) | (ow[2] >> 31);
        *((uint4*)&g_s5[((size_t)(n * 3200 + tid * 100 + px)) * 4]) =
            make_uint4(d0, d1, d2, d3);
    }
}

// ---------------------------------------------------------------------------
// K5b: bit transpose t-major -> c-major via ballot (FC input).
// ---------------------------------------------------------------------------
__global__ void k_trans() {
    int gw = (blockIdx.x * blockDim.x + threadIdx.x) >> 5;   // 0..6399
    int lane = threadIdx.x & 31;
    int n = gw / 400;
    int r = gw % 400;
    int cw = r >> 2;
    int j = r & 3;
    uint32_t w = g_s5[((size_t)n * 3200 + cw * 32 + lane) * 4 + j];
    uint32_t out = 0;
#pragma unroll
    for (int b = 0; b < 32; b++) {
        uint32_t bl = __ballot_sync(0xffffffffu, (w >> b) & 1u);
        if (lane == b) out = bl;
    }
    g_sb[((size_t)n * 128 + j * 32 + lane) * 100 + cw] = out;
}

// ---------------------------------------------------------------------------
// K6: sparse FC, o-pair + 64-t accumulators (cuts W restage 4x -> 210MB).
// grid = (2 tt, 16 n, 4 cs); block 256 threads, thread = o-pair (2tid, 2tid+1).
// Per-(o,t) summation order identical to round-3 kernel.
// ---------------------------------------------------------------------------
__global__ void __launch_bounds__(256, 1) k_fcs2(const float* __restrict__ W,
                                                 float* __restrict__ x6p) {
    extern __shared__ float2 shW2[];        // [32 c][256 o-pairs] = 64KB
    __shared__ uint32_t shB[64 * 25];

    int tt = blockIdx.x, n = blockIdx.y, cs = blockIdx.z;
    int tid = threadIdx.x;
    int o0 = 2 * tid;

    for (int i = tid; i < 64 * 25; i += 256) {
        int b = i / 25, cc = i % 25;
        shB[i] = g_sb[((size_t)n * 128 + tt * 64 + b) * 100 + cs * 25 + cc];
    }

    float2 acc[64];
#pragma unroll
    for (int t = 0; t < 64; t++) acc[t] = make_float2(0.f, 0.f);

    const float* w0 = W + (size_t)o0 * 3200 + cs * 800;
    const float* w1 = w0 + 3200;

    for (int cc = 0; cc < 25; cc++) {
        __syncthreads();
        const float4* p0 = (const float4*)(w0 + cc * 32);
        const float4* p1 = (const float4*)(w1 + cc * 32);
#pragma unroll
        for (int q = 0; q < 8; q++) {
            float4 a = p0[q], b = p1[q];
            shW2[(q * 4 + 0) * 256 + tid] = make_float2(a.x, b.x);
            shW2[(q * 4 + 1) * 256 + tid] = make_float2(a.y, b.y);
            shW2[(q * 4 + 2) * 256 + tid] = make_float2(a.z, b.z);
            shW2[(q * 4 + 3) * 256 + tid] = make_float2(a.w, b.w);
        }
        __syncthreads();

#pragma unroll
        for (int t = 0; t < 64; t++) {
            uint32_t s = shB[t * 25 + cc];
            while (s) {
                int k = __ffs(s) - 1;
                s &= s - 1;
                float2 w2 = shW2[k * 256 + tid];
                acc[t].x += w2.x;
                acc[t].y += w2.y;
            }
        }
    }

    float* r0 = x6p + ((size_t)((cs * 16 + n) * 512 + o0)) * 128 + tt * 64;
    float* r1 = r0 + 128;
#pragma unroll
    for (int q = 0; q < 16; q++) {
        ((float4*)r0)[q] = make_float4(acc[4*q].x, acc[4*q+1].x, acc[4*q+2].x, acc[4*q+3].x);
        ((float4*)r1)[q] = make_float4(acc[4*q].y, acc[4*q+1].y, acc[4*q+2].y, acc[4*q+3].y);
    }
}

// ---------------------------------------------------------------------------
// K7: final LIF over sum of 4 partials + output delay-shift -> d_out
// ---------------------------------------------------------------------------
__global__ void k_lif_out(const float* __restrict__ x6p, float* __restrict__ out) {
    const size_t S = (size_t)16 * 512 * 128;
    int idx = blockIdx.x * blockDim.x + threadIdx.x;   // (n,o), 8192 total
    const float* a = &x6p[(size_t)idx * 128];
    float* op = &out[(size_t)idx * 128];
    float u = 0.f, v = 0.f, prev = 0.f;
#pragma unroll 8
    for (int t = 0; t < 128; t++) {
        op[t] = prev;
        float x = (a[t] + a[t + S]) + (a[t + 2 * S] + a[t + 3 * S]);
        u = AI * u + x;
        v = AV * v + u;
        if (v >= TH) { prev = 1.f; v = 0.f; } else { prev = 0.f; }
    }
}

// ---------------------------------------------------------------------------
extern "C" void kernel_launch(void* const* d_in, const int* in_sizes, int n_in,
                              void* d_out, int out_size) {
    const float* spike = (const float*)d_in[0];
    const float* c1w   = (const float*)d_in[1];
    const float* c2w   = (const float*)d_in[2];
    const float* c3w   = (const float*)d_in[3];
    const float* p1w   = (const float*)d_in[4];
    const float* p2w   = (const float*)d_in[5];
    const float* fcw   = (const float*)d_in[6];
    float* out = (float*)d_out;

    uint32_t *s1, *s2, *s3, *s4;
    float* x6p;
    cudaGetSymbolAddress((void**)&s1, g_s1);
    cudaGetSymbolAddress((void**)&s2, g_s2);
    cudaGetSymbolAddress((void**)&s3, g_s3);
    cudaGetSymbolAddress((void**)&s4, g_s4);
    cudaGetSymbolAddress((void**)&x6p, g_x6p);

    cudaFuncSetAttribute((const void*)k_fcs2,
                         cudaFuncAttributeMaxDynamicSharedMemorySize, 65536);

    k_pack<<<200, 256>>>(spike);
    k_conv1<<<640, 320>>>(c1w);
    k_pool<<<200, 256>>>(s1, s2, 8, 40, p1w);         // -> g_s2
    k_tr8<<<100, 256>>>();                             // g_s2 -> g_cp1 (padded bytes)
    k_conv2s<<<dim3(400, 16), 128>>>(c2w);             // -> g_s3
    k_pool<<<100, 256>>>(s3, s4, 16, 20, p2w);         // -> g_s4
    k_tr16<<<25, 256>>>();                             // g_s4 -> g_cp2 (padded u16)
    k_conv3s<<<dim3(100, 16), 256>>>(c3w);             // -> g_s5
    k_trans<<<800, 256>>>();                           // g_s5 -> g_sb
    k_fcs2<<<dim3(2, 16, 4), 256, 65536>>>(fcw, x6p);  // -> x6p (4 partials)
    k_lif_out<<<32, 256>>>(x6p, out);
}

// round 5
// speedup vs baseline: 2.3510x; 1.0564x over previous
#include <cuda_runtime.h>
#include <stdint.h>

// Loihi CUBA constants
#define AI 0.75f       // (4096-1024)/4096
#define AV 0.96875f    // (4096-128)/4096
#define TH 100.0f

__device__ __forceinline__ void add2(unsigned long long& a, unsigned long long b) {
    asm("add.rn.f32x2 %0, %0, %1;" : "+l"(a) : "l"(b));
}
__device__ __forceinline__ float2 u64f2(unsigned long long v) {
    float2 f; asm("mov.b64 {%0, %1}, %2;" : "=f"(f.x), "=f"(f.y) : "l"(v)); return f;
}

// ---------------------------------------------------------------------------
// Bitpacked spike buffers: bit k of word j (of 4) = spike at t = j*32 + k.
// All intermediate buffers store the DELAYED stream (128-bit <<1 done at
// producer write time).
// ---------------------------------------------------------------------------
__device__ uint32_t g_s0[16 * 2  * 40 * 40 * 4];   // packed raw input spikes
__device__ uint32_t g_s1[16 * 8  * 40 * 40 * 4];   // conv1+LIF out (delayed)
__device__ uint32_t g_s2[16 * 8  * 20 * 20 * 4];   // pool1+LIF out (delayed)
__device__ uint32_t g_s3[16 * 16 * 20 * 20 * 4];   // conv2+LIF out (delayed)
__device__ uint32_t g_s4[16 * 16 * 10 * 10 * 4];   // pool2+LIF out (delayed)
__device__ uint32_t g_s5[16 * 3200 * 4];           // conv3+LIF out (delayed, t-major)
__device__ uint32_t g_sb[16 * 128 * 100];          // FC input: c-major words per (n,t)
// c-major padded spike images (pads stay zero: zero-init, never written)
__device__ uint8_t  g_cp1[16 * 22 * 22 * 128];     // pool1 out, 8 c bits per (n,py,px,t)
__device__ uint16_t g_cp2[16 * 12 * 12 * 128];     // pool2 out, 16 c bits per (n,py,px,t)
__device__ float    g_x6p[4 * 16 * 512 * 128];     // fc pre-activations (4 c-quarter partials)

// ---------------------------------------------------------------------------
// K0: pack raw float spikes [16,2,40,40,128] (t contiguous) -> bit words
// ---------------------------------------------------------------------------
__global__ void k_pack(const float* __restrict__ sp) {
    int idx = blockIdx.x * blockDim.x + threadIdx.x;   // (n,c,h,w), 51200 total
    const float4* p = (const float4*)(sp + (size_t)idx * 128);
    uint32_t w[4];
#pragma unroll
    for (int j = 0; j < 4; j++) {
        uint32_t b = 0;
#pragma unroll
        for (int q = 0; q < 8; q++) {
            float4 v = p[j * 8 + q];
            b |= (v.x > 0.5f ? 1u : 0u) << (q * 4 + 0);
            b |= (v.y > 0.5f ? 1u : 0u) << (q * 4 + 1);
            b |= (v.z > 0.5f ? 1u : 0u) << (q * 4 + 2);
            b |= (v.w > 0.5f ? 1u : 0u) << (q * 4 + 3);
        }
        w[j] = b;
    }
    *((uint4*)&g_s0[(size_t)idx * 4]) = make_uint4(w[0], w[1], w[2], w[3]);
}

// ---------------------------------------------------------------------------
// K1: conv1 (2->8, 3x3, pad1, w*20) + LIF -> g_s1 (delayed). Dense bit path.
// grid = 16n * 40h ; block = 40w * 8o = 320 threads
// ---------------------------------------------------------------------------
__global__ void k_conv1(const float* __restrict__ cw) {
    __shared__ uint32_t sh[2 * 3 * 42 * 4];  // [c][dy][wx(42, halo)][j]
    int b = blockIdx.x;
    int n = b / 40, h = b % 40;
    int tid = threadIdx.x;

    for (int i = tid; i < 2 * 3 * 42 * 4; i += 320) {
        int j = i & 3;
        int t2 = i >> 2;
        int wx = t2 % 42;
        int t3 = t2 / 42;
        int dy = t3 % 3;
        int c  = t3 / 3;
        int r = h - 1 + dy, ws = wx - 1;
        uint32_t v = 0;
        if (r >= 0 && r < 40 && ws >= 0 && ws < 40)
            v = g_s0[(((n * 2 + c) * 40 + r) * 40 + ws) * 4 + j];
        sh[i] = v;
    }
    __syncthreads();

    int w = tid % 40, o = tid / 40;
    float wg[18];
#pragma unroll
    for (int i = 0; i < 18; i++) wg[i] = cw[o * 18 + i] * 20.0f;

    float u = 0.f, v = 0.f;
    uint32_t ow[4];
#pragma unroll
    for (int j = 0; j < 4; j++) {
        float acc[32];
#pragma unroll
        for (int k = 0; k < 32; k++) acc[k] = 0.f;
#pragma unroll
        for (int c = 0; c < 2; c++)
#pragma unroll
        for (int dy = 0; dy < 3; dy++)
#pragma unroll
        for (int dx = 0; dx < 3; dx++) {
            uint32_t wd = sh[(((c * 3 + dy) * 42) + (w + dx)) * 4 + j];
            float wt = wg[c * 9 + dy * 3 + dx];
#pragma unroll
            for (int k = 0; k < 32; k++)
                if (wd & (1u << k)) acc[k] += wt;
        }
        uint32_t bits = 0;
#pragma unroll
        for (int k = 0; k < 32; k++) {
            u = AI * u + acc[k];
            v = AV * v + u;
            if (v >= TH) { bits |= 1u << k; v = 0.f; }
        }
        ow[j] = bits;
    }
    uint32_t d0 = ow[0] << 1;
    uint32_t d1 = (ow[1] << 1) | (ow[0] >> 31);
    uint32_t d2 = (ow[2] << 1) | (ow[1] >> 31);
    uint32_t d3 = (ow[3] << 1) | (ow[2] >> 31);
    *((uint4*)&g_s1[((((n * 8 + o) * 40 + h) * 40 + w)) * 4]) = make_uint4(d0, d1, d2, d3);
}

// ---------------------------------------------------------------------------
// K2: 2x2 sum pool (* pool_w scalar) + LIF -> out (delayed). Generic.
// ---------------------------------------------------------------------------
__global__ void k_pool(const uint32_t* __restrict__ in, uint32_t* __restrict__ out,
                       int C, int Hin, const float* __restrict__ pw) {
    int Ho = Hin / 2;
    int idx = blockIdx.x * blockDim.x + threadIdx.x;   // (n,c,ph,pw)
    int pwi = idx % Ho;
    int t = idx / Ho;
    int phi = t % Ho; t /= Ho;
    int c = t % C;
    int n = t / C;
    float scale = pw[0];

    const uint32_t* b00 = &in[((((n * C + c) * Hin + 2 * phi) * Hin) + 2 * pwi) * 4];
    const uint32_t* b10 = b00 + Hin * 4;

    float u = 0.f, v = 0.f;
    uint32_t ow[4];
#pragma unroll
    for (int j = 0; j < 4; j++) {
        uint32_t a = b00[j], bb = b00[4 + j], cc = b10[j], d = b10[4 + j];
        uint32_t bits = 0;
#pragma unroll
        for (int k = 0; k < 32; k++) {
            int cnt = (int)((a >> k) & 1u) + (int)((bb >> k) & 1u)
                    + (int)((cc >> k) & 1u) + (int)((d >> k) & 1u);
            float x = (float)cnt * scale;
            u = AI * u + x;
            v = AV * v + u;
            if (v >= TH) { bits |= 1u << k; v = 0.f; }
        }
        ow[j] = bits;
    }
    uint32_t d0 = ow[0] << 1;
    uint32_t d1 = (ow[1] << 1) | (ow[0] >> 31);
    uint32_t d2 = (ow[2] << 1) | (ow[1] >> 31);
    uint32_t d3 = (ow[3] << 1) | (ow[2] >> 31);
    *((uint4*)&out[(size_t)idx * 4]) = make_uint4(d0, d1, d2, d3);
}

// ---------------------------------------------------------------------------
// K2b: transpose pool1 out (t-major bits per c) -> c-major bytes, padded 22x22.
// ---------------------------------------------------------------------------
__global__ void k_tr8() {
    int i = blockIdx.x * blockDim.x + threadIdx.x;   // 25600
    int n = i / 1600;
    int r = i % 1600;
    int px = r >> 2, j = r & 3;
    uint32_t wc[8];
#pragma unroll
    for (int c = 0; c < 8; c++)
        wc[c] = g_s2[((size_t)((n * 8 + c) * 400 + px)) * 4 + j];
    int h = px / 20, w = px % 20;
    uint8_t* dst = g_cp1 + ((size_t)n * 484 + (h + 1) * 22 + (w + 1)) * 128 + j * 32;
#pragma unroll
    for (int k = 0; k < 32; k += 4) {
        uint32_t v = 0;
#pragma unroll
        for (int q = 0; q < 4; q++) {
            uint32_t byte = 0;
#pragma unroll
            for (int c = 0; c < 8; c++)
                byte |= ((wc[c] >> (k + q)) & 1u) << c;
            v |= byte << (q * 8);
        }
        *(uint32_t*)(dst + k) = v;
    }
}

// ---------------------------------------------------------------------------
// K4b: transpose pool2 out -> c-major uint16, padded 12x12.
// ---------------------------------------------------------------------------
__global__ void k_tr16() {
    int i = blockIdx.x * blockDim.x + threadIdx.x;   // 6400
    int n = i / 400;
    int r = i % 400;
    int px = r >> 2, j = r & 3;
    uint32_t wc[16];
#pragma unroll
    for (int c = 0; c < 16; c++)
        wc[c] = g_s4[((size_t)((n * 16 + c) * 100 + px)) * 4 + j];
    int h = px / 10, w = px % 10;
    uint16_t* dst = g_cp2 + ((size_t)n * 144 + (h + 1) * 12 + (w + 1)) * 128 + j * 32;
#pragma unroll
    for (int k = 0; k < 32; k += 2) {
        uint32_t v = 0;
#pragma unroll
        for (int c = 0; c < 16; c++) {
            v |= ((wc[c] >> k) & 1u) << c;
            v |= ((wc[c] >> (k + 1)) & 1u) << (16 + c);
        }
        *(uint32_t*)(dst + k) = v;
    }
}

// ---------------------------------------------------------------------------
// K3: sparse conv2 (8->16, w*100) + LIF -> g_s3. o-quad + f32x2 adds.
// grid = (400 px, 16 n); block 128 = 4 quads x 32 tq (4 t each).
// tap = (dy*3+dx)*8 + c; same ascending-tap order as round 4 (bit-identical).
// ---------------------------------------------------------------------------
__global__ void __launch_bounds__(128) k_conv2s(const float* __restrict__ wsrc) {
    __shared__ float4   shW4[72 * 4];        // [tap][quad] -> w for o=4q..4q+3
    __shared__ uint32_t shTW[128 * 3];
    __shared__ float    pre[16 * 129];
    int px = blockIdx.x, n = blockIdx.y;
    int h = px / 20, w = px % 20;
    int tid = threadIdx.x;

    for (int i = tid; i < 72 * 4; i += 128) {
        int q = i & 3, tap = i >> 2;
        int c = tap & 7, dydx = tap >> 3;
        float4 v;
        v.x = wsrc[((4 * q + 0) * 8 + c) * 9 + dydx] * 100.0f;
        v.y = wsrc[((4 * q + 1) * 8 + c) * 9 + dydx] * 100.0f;
        v.z = wsrc[((4 * q + 2) * 8 + c) * 9 + dydx] * 100.0f;
        v.w = wsrc[((4 * q + 3) * 8 + c) * 9 + dydx] * 100.0f;
        shW4[i] = v;
    }
    {   // build 3 tap words for t = tid
        const uint8_t* base = g_cp1 + ((size_t)n * 484 + h * 22 + w) * 128 + tid;
        uint32_t b[9];
#pragma unroll
        for (int dy = 0; dy < 3; dy++)
#pragma unroll
            for (int dx = 0; dx < 3; dx++)
                b[dy * 3 + dx] = base[(dy * 22 + dx) * 128];
        shTW[tid * 3 + 0] = b[0] | (b[1] << 8) | (b[2] << 16) | (b[3] << 24);
        shTW[tid * 3 + 1] = b[4] | (b[5] << 8) | (b[6] << 16) | (b[7] << 24);
        shTW[tid * 3 + 2] = b[8];
    }
    __syncthreads();

    int q = tid & 3, tq = tid >> 2;
#pragma unroll
    for (int i = 0; i < 4; i++) {
        int t = tq * 4 + i;
        uint32_t s0 = shTW[t * 3], s1 = shTW[t * 3 + 1], s2 = shTW[t * 3 + 2];
        unsigned long long a0 = 0ull, a1 = 0ull;
        while (s0) {
            int k = __ffs(s0) - 1; s0 &= s0 - 1;
            const ulonglong2 wv = *(const ulonglong2*)&shW4[k * 4 + q];
            add2(a0, wv.x); add2(a1, wv.y);
        }
        while (s1) {
            int k = __ffs(s1) - 1; s1 &= s1 - 1;
            const ulonglong2 wv = *(const ulonglong2*)&shW4[(32 + k) * 4 + q];
            add2(a0, wv.x); add2(a1, wv.y);
        }
        while (s2) {
            int k = __ffs(s2) - 1; s2 &= s2 - 1;
            const ulonglong2 wv = *(const ulonglong2*)&shW4[(64 + k) * 4 + q];
            add2(a0, wv.x); add2(a1, wv.y);
        }
        float2 f0 = u64f2(a0), f1 = u64f2(a1);
        pre[(4 * q + 0) * 129 + t] = f0.x;
        pre[(4 * q + 1) * 129 + t] = f0.y;
        pre[(4 * q + 2) * 129 + t] = f1.x;
        pre[(4 * q + 3) * 129 + t] = f1.y;
    }
    __syncthreads();

    if (tid < 16) {
        float u = 0.f, v = 0.f;
        uint32_t ow[4];
#pragma unroll
        for (int j = 0; j < 4; j++) {
            uint32_t bits = 0;
#pragma unroll
            for (int k = 0; k < 32; k++) {
                u = AI * u + pre[tid * 129 + j * 32 + k];
                v = AV * v + u;
                if (v >= TH) { bits |= 1u << k; v = 0.f; }
            }
            ow[j] = bits;
        }
        uint32_t d0 = ow[0] << 1;
        uint32_t d1 = (ow[1] << 1) | (ow[0] >> 31);
        uint32_t d2 = (ow[2] << 1) | (ow[1] >> 31);
        uint32_t d3 = (ow[3] << 1) | (ow[2] >> 31);
        *((uint4*)&g_s3[((size_t)((n * 16 + tid) * 400 + px)) * 4]) =
            make_uint4(d0, d1, d2, d3);
    }
}

// ---------------------------------------------------------------------------
// K5: sparse conv3 (16->32, w*100) + LIF -> g_s5. o-quad + f32x2 adds.
// grid = (100 px, 16 n); block 128 = 8 quads x 16 tq (8 t each).
// tap = (dy*3+dx)*16 + c.
// ---------------------------------------------------------------------------
__global__ void __launch_bounds__(128) k_conv3s(const float* __restrict__ wsrc) {
    __shared__ float4   shW4[144 * 8];       // [tap][quad]
    __shared__ uint32_t shTW[128 * 5];
    __shared__ float    pre[32 * 129];
    int px = blockIdx.x, n = blockIdx.y;
    int h = px / 10, w = px % 10;
    int tid = threadIdx.x;

    for (int i = tid; i < 144 * 8; i += 128) {
        int q = i & 7, tap = i >> 3;
        int c = tap & 15, dydx = tap >> 4;
        float4 v;
        v.x = wsrc[((4 * q + 0) * 16 + c) * 9 + dydx] * 100.0f;
        v.y = wsrc[((4 * q + 1) * 16 + c) * 9 + dydx] * 100.0f;
        v.z = wsrc[((4 * q + 2) * 16 + c) * 9 + dydx] * 100.0f;
        v.w = wsrc[((4 * q + 3) * 16 + c) * 9 + dydx] * 100.0f;
        shW4[i] = v;
    }
    {
        const uint16_t* base = g_cp2 + ((size_t)n * 144 + h * 12 + w) * 128 + tid;
        uint32_t b[9];
#pragma unroll
        for (int dy = 0; dy < 3; dy++)
#pragma unroll
            for (int dx = 0; dx < 3; dx++)
                b[dy * 3 + dx] = base[(dy * 12 + dx) * 128];
        shTW[tid * 5 + 0] = b[0] | (b[1] << 16);
        shTW[tid * 5 + 1] = b[2] | (b[3] << 16);
        shTW[tid * 5 + 2] = b[4] | (b[5] << 16);
        shTW[tid * 5 + 3] = b[6] | (b[7] << 16);
        shTW[tid * 5 + 4] = b[8];
    }
    __syncthreads();

    int q = tid & 7, tq = tid >> 3;
#pragma unroll
    for (int i = 0; i < 8; i++) {
        int t = tq * 8 + i;
        unsigned long long a0 = 0ull, a1 = 0ull;
#pragma unroll
        for (int m = 0; m < 5; m++) {
            uint32_t s = shTW[t * 5 + m];
            while (s) {
                int k = __ffs(s) - 1; s &= s - 1;
                const ulonglong2 wv = *(const ulonglong2*)&shW4[(m * 32 + k) * 8 + q];
                add2(a0, wv.x); add2(a1, wv.y);
            }
        }
        float2 f0 = u64f2(a0), f1 = u64f2(a1);
        pre[(4 * q + 0) * 129 + t] = f0.x;
        pre[(4 * q + 1) * 129 + t] = f0.y;
        pre[(4 * q + 2) * 129 + t] = f1.x;
        pre[(4 * q + 3) * 129 + t] = f1.y;
    }
    __syncthreads();

    if (tid < 32) {
        float u = 0.f, v = 0.f;
        uint32_t ow[4];
#pragma unroll
        for (int j = 0; j < 4; j++) {
            uint32_t bits = 0;
#pragma unroll
            for (int k = 0; k < 32; k++) {
                u = AI * u + pre[tid * 129 + j * 32 + k];
                v = AV * v + u;
                if (v >= TH) { bits |= 1u << k; v = 0.f; }
            }
            ow[j] = bits;
        }
        uint32_t d0 = ow[0] << 1;
        uint32_t d1 = (ow[1] << 1) | (ow[0] >> 31);
        uint32_t d2 = (ow[2] << 1) | (ow[1] >> 31);
        uint32_t d3 = (ow[3] << 1) | (ow[2] >> 31);
        *((uint4*)&g_s5[((size_t)(n * 3200 + tid * 100 + px)) * 4]) =
            make_uint4(d0, d1, d2, d3);
    }
}

// ---------------------------------------------------------------------------
// K5b: bit transpose t-major -> c-major via ballot (FC input).
// ---------------------------------------------------------------------------
__global__ void k_trans() {
    int gw = (blockIdx.x * blockDim.x + threadIdx.x) >> 5;   // 0..6399
    int lane = threadIdx.x & 31;
    int n = gw / 400;
    int r = gw % 400;
    int cw = r >> 2;
    int j = r & 3;
    uint32_t w = g_s5[((size_t)n * 3200 + cw * 32 + lane) * 4 + j];
    uint32_t out = 0;
#pragma unroll
    for (int b = 0; b < 32; b++) {
        uint32_t bl = __ballot_sync(0xffffffffu, (w >> b) & 1u);
        if (lane == b) out = bl;
    }
    g_sb[((size_t)n * 128 + j * 32 + lane) * 100 + cw] = out;
}

// ---------------------------------------------------------------------------
// K6: sparse FC, o-quad + f32x2. grid = (2 tt, 16 n, 4 cs); block 512.
// Thread roles: inner = (quad q = tid&127 -> o 4q..4q+3, th = tid>>7 -> 16 t).
// Staging identical W layout to round 4: shW2[c][256 pairs]; quad reads
// LDS.128 at pair 2q (o 4q..4q+3). Per-(o,t) summation order unchanged.
// W L2 traffic: 128 blocks x 1.6MB = 210MB (same as round 4).
// ---------------------------------------------------------------------------
__global__ void __launch_bounds__(512, 1) k_fcq(const float* __restrict__ W,
                                                float* __restrict__ x6p) {
    extern __shared__ float2 shW2[];        // [32 c][256 o-pairs] = 64KB
    __shared__ uint32_t shB[64 * 25];

    int tt = blockIdx.x, n = blockIdx.y, cs = blockIdx.z;
    int tid = threadIdx.x;

    for (int i = tid; i < 64 * 25; i += 512) {
        int b = i / 25, cc = i % 25;
        shB[i] = g_sb[((size_t)n * 128 + tt * 64 + b) * 100 + cs * 25 + cc];
    }

    int q  = tid & 127;     // o-quad: o = 4q..4q+3
    int th = tid >> 7;      // 0..3: t-range = tt*64 + th*16 + [0,16)

    unsigned long long acc0[16], acc1[16];
#pragma unroll
    for (int i = 0; i < 16; i++) { acc0[i] = 0ull; acc1[i] = 0ull; }

    // staging role: pair pr = tid&255, c-half ch = tid>>8
    int pr = tid & 255, ch = tid >> 8;
    const float* w0 = W + (size_t)(2 * pr) * 3200 + cs * 800 + ch * 16;
    const float* w1 = w0 + 3200;

    for (int cc = 0; cc < 25; cc++) {
        __syncthreads();
        const float4* p0 = (const float4*)(w0 + cc * 32);
        const float4* p1 = (const float4*)(w1 + cc * 32);
#pragma unroll
        for (int qq = 0; qq < 4; qq++) {
            float4 a = p0[qq], b = p1[qq];
            int c0 = ch * 16 + qq * 4;
            shW2[(c0 + 0) * 256 + pr] = make_float2(a.x, b.x);
            shW2[(c0 + 1) * 256 + pr] = make_float2(a.y, b.y);
            shW2[(c0 + 2) * 256 + pr] = make_float2(a.z, b.z);
            shW2[(c0 + 3) * 256 + pr] = make_float2(a.w, b.w);
        }
        __syncthreads();

#pragma unroll
        for (int i = 0; i < 16; i++) {
            uint32_t s = shB[(th * 16 + i) * 25 + cc];
            while (s) {
                int k = __ffs(s) - 1;
                s &= s - 1;
                const ulonglong2 wv = *(const ulonglong2*)&shW2[k * 256 + 2 * q];
                add2(acc0[i], wv.x);
                add2(acc1[i], wv.y);
            }
        }
    }

    float* base = x6p + ((size_t)((cs * 16 + n) * 512 + 4 * q)) * 128 + tt * 64 + th * 16;
#pragma unroll
    for (int i = 0; i < 16; i++) {
        float2 f0 = u64f2(acc0[i]);
        float2 f1 = u64f2(acc1[i]);
        base[0 * 128 + i] = f0.x;
        base[1 * 128 + i] = f0.y;
        base[2 * 128 + i] = f1.x;
        base[3 * 128 + i] = f1.y;
    }
}

// ---------------------------------------------------------------------------
// K7: final LIF over sum of 4 partials + output delay-shift -> d_out
// ---------------------------------------------------------------------------
__global__ void k_lif_out(const float* __restrict__ x6p, float* __restrict__ out) {
    const size_t S = (size_t)16 * 512 * 128;
    int idx = blockIdx.x * blockDim.x + threadIdx.x;   // (n,o), 8192 total
    const float* a = &x6p[(size_t)idx * 128];
    float* op = &out[(size_t)idx * 128];
    float u = 0.f, v = 0.f, prev = 0.f;
#pragma unroll 8
    for (int t = 0; t < 128; t++) {
        op[t] = prev;
        float x = (a[t] + a[t + S]) + (a[t + 2 * S] + a[t + 3 * S]);
        u = AI * u + x;
        v = AV * v + u;
        if (v >= TH) { prev = 1.f; v = 0.f; } else { prev = 0.f; }
    }
}

// ---------------------------------------------------------------------------
extern "C" void kernel_launch(void* const* d_in, const int* in_sizes, int n_in,
                              void* d_out, int out_size) {
    const float* spike = (const float*)d_in[0];
    const float* c1w   = (const float*)d_in[1];
    const float* c2w   = (const float*)d_in[2];
    const float* c3w   = (const float*)d_in[3];
    const float* p1w   = (const float*)d_in[4];
    const float* p2w   = (const float*)d_in[5];
    const float* fcw   = (const float*)d_in[6];
    float* out = (float*)d_out;

    uint32_t *s1, *s2, *s3, *s4;
    float* x6p;
    cudaGetSymbolAddress((void**)&s1, g_s1);
    cudaGetSymbolAddress((void**)&s2, g_s2);
    cudaGetSymbolAddress((void**)&s3, g_s3);
    cudaGetSymbolAddress((void**)&s4, g_s4);
    cudaGetSymbolAddress((void**)&x6p, g_x6p);

    cudaFuncSetAttribute((const void*)k_fcq,
                         cudaFuncAttributeMaxDynamicSharedMemorySize, 65536);

    k_pack<<<200, 256>>>(spike);
    k_conv1<<<640, 320>>>(c1w);
    k_pool<<<200, 256>>>(s1, s2, 8, 40, p1w);          // -> g_s2
    k_tr8<<<100, 256>>>();                              // g_s2 -> g_cp1
    k_conv2s<<<dim3(400, 16), 128>>>(c2w);              // -> g_s3 (o-quad)
    k_pool<<<100, 256>>>(s3, s4, 16, 20, p2w);          // -> g_s4
    k_tr16<<<25, 256>>>();                              // g_s4 -> g_cp2
    k_conv3s<<<dim3(100, 16), 128>>>(c3w);              // -> g_s5 (o-quad)
    k_trans<<<800, 256>>>();                            // g_s5 -> g_sb
    k_fcq<<<dim3(2, 16, 4), 512, 65536>>>(fcw, x6p);    // -> x6p (o-quad)
    k_lif_out<<<32, 256>>>(x6p, out);
}